// round 16
// baseline (speedup 1.0000x reference)
#include <cuda_runtime.h>

// MWPT: 3-level wavelet packet transform, fused, polyphase smem layout.
// Structure = R10/R15 (best verified). ALL levels fma.rn.f32x2:
//   level 1: lanes = (lo,hi) filters; accumulator pair IS the stored (a0,a4).
//   levels 2-3: lanes = parent pairs over sub-parity-split arrays
//            (16B-stride LDS, conflict-free), coefficients broadcast.
// R15: __stcs streaming output stores (validated: cut L2 dirty-drain tail,
//      wall 26.9 -> 23.2us). R16: __ldcs streaming x reads (read-once data;
//      keep L2 capacity for output write buffering).
//
// conv: out[n] = sum_k in[(2n + k - 3) mod L] * w[k]  (circular, stride 2)
// hi-pass QMF: wh[k] = (-1)^k * wl[7-k]
// out = concat(level1 [128,2,32768], level2 [128,4,16384], level3 [128,8,8192])
// level2 node order [b0,b2,b6,b4]; level3 [c0,c1,c3,c2,c6,c7,c5,c4].
//
// Index algebra (validated R3-R15):
//  x staged from jbase=8n0-28: xE[i]=x[jbase+2i], xO[i]=x[jbase+2i+1]
//  a_alpha (alpha=m-4n0+12) = sum_j xO[alpha+j]wl[2j] + xE[alpha+j+1]wl[2j+1]
//    chunk G: alpha=4G+p; owned G in [3,515); halo {0,1,2,515,516,517}
//    pairs P[alpha]=(a0,a4): aEe[G]=P[4G], aOe[G]=P[4G+1], aEo[G]=P[4G+2], aOo[G]=P[4G+3]
//  b_beta (beta=l-2n0+4): lanes (a0,a4) -> fam0=(b0,b4), fam1=(b2,b6)
//    chunk h: beta=4h+p -> bEe[h],bOe[h],bEo[h],bOo[h]; owned h in [1,257)
//  c_r (r=i-n0) in [0,512): from fam arrays, chunk q: r=4q+p

namespace {
constexpr int T   = 65536, MSK = T - 1, KS = 8;
constexpr int N3  = 512;
constexpr int THREADS = 256;
constexpr int XSZ  = 2080;              // floats per x parity
constexpr int XREG = 2 * XSZ;           // 4160 floats; aliased by b sub-arrays
constexpr int ASUB = 520;               // float2 per a sub-array (518 used), x4
constexpr int BSUB = 260;               // float2 per b sub-array (258 used), x8
constexpr int SMEM_FLOATS = XREG + 4 * ASUB * 2;   // 8320
constexpr int SMEM_BYTES  = SMEM_FLOATS * 4;       // 33280
constexpr long OUT2_BASE = 128L * 2 * 32768;
constexpr long OUT3_BASE = OUT2_BASE + 128L * 4 * 16384;
}

using u64 = unsigned long long;
union F2U { u64 u; float2 f; };

__device__ __forceinline__ u64 bcast2(float a) {
    u64 r; asm("mov.b64 %0, {%1, %1};" : "=l"(r) : "f"(a)); return r;
}
__device__ __forceinline__ u64 pack2(float a, float b) {
    u64 r; asm("mov.b64 %0, {%1, %2};" : "=l"(r) : "f"(a), "f"(b)); return r;
}
__device__ __forceinline__ u64 mul2(u64 a, u64 b) {
    u64 d; asm("mul.rn.f32x2 %0, %1, %2;" : "=l"(d) : "l"(a), "l"(b)); return d;
}
__device__ __forceinline__ void fma2(u64& d, u64 a, u64 b) {
    asm("fma.rn.f32x2 %0, %1, %2, %0;" : "+l"(d) : "l"(a), "l"(b));
}

__device__ __forceinline__ void ld8(const float* s, float v[8]) {
    float4 a = *(const float4*)s;
    float4 b = *(const float4*)(s + 4);
    v[0]=a.x; v[1]=a.y; v[2]=a.z; v[3]=a.w;
    v[4]=b.x; v[5]=b.y; v[6]=b.z; v[7]=b.w;
}
// 4 consecutive float2: 2x LDS.128 at 16B/thread stride (conflict-free).
__device__ __forceinline__ void ld4p(const float2* s, int i, u64 v[4]) {
    const ulonglong2* p = (const ulonglong2*)(s + i);
    ulonglong2 q0 = p[0], q1 = p[1];
    v[0]=q0.x; v[1]=q0.y; v[2]=q1.x; v[3]=q1.y;
}
// streaming 128-bit store (evict-first; output is write-once)
__device__ __forceinline__ void stg4s(float* p, float a, float b, float c, float d) {
    __stcs((float4*)p, make_float4(a, b, c, d));
}

// Level-1 packed chunk: acc[p] = (lo,hi) pair for alpha = 4G+p.
__device__ __forceinline__ void qmf4f(const float o8[8], const float e8[8],
                                      const u64 wp[KS], u64 acc[4]) {
    #pragma unroll
    for (int p = 0; p < 4; ++p) {
        u64 a = mul2(bcast2(o8[p]), wp[0]);     // bcasts CSE across p
        fma2(a, bcast2(e8[p+1]), wp[1]);
        #pragma unroll
        for (int j = 1; j < 4; ++j) {
            fma2(a, bcast2(o8[p+j]),   wp[2*j]);
            fma2(a, bcast2(e8[p+j+1]), wp[2*j+1]);
        }
        acc[p] = a;
    }
}

// packed 2-lane QMF (lanes = two parent nodes, coefficients broadcast)
__device__ __forceinline__ void qmf4p(const u64 O[8], const u64 E[8],
                                      const u64 bl[KS], const u64 bh[KS],
                                      u64 aL[4], u64 aH[4]) {
    #pragma unroll
    for (int p = 0; p < 4; ++p) {
        u64 l = mul2(O[p], bl[0]);
        u64 h = mul2(O[p], bh[0]);
        fma2(l, E[p+1], bl[1]);
        fma2(h, E[p+1], bh[1]);
        #pragma unroll
        for (int j = 1; j < 4; ++j) {
            fma2(l, O[p+j],   bl[2*j]);   fma2(l, E[p+j+1], bl[2*j+1]);
            fma2(h, O[p+j],   bh[2*j]);   fma2(h, E[p+j+1], bh[2*j+1]);
        }
        aL[p] = l; aH[p] = h;
    }
}

__global__ __launch_bounds__(THREADS, 4) void mwpt_kernel(
    const float* __restrict__ x,
    const float* __restrict__ kern,
    float* __restrict__ out)
{
    extern __shared__ float sm[];
    float*  xE  = sm;                          // [XSZ]
    float*  xO  = sm + XSZ;                    // [XSZ]
    float2* aEe = (float2*)(sm + XREG);        // [ASUB] each
    float2* aOe = aEe + ASUB;
    float2* aEo = aOe + ASUB;
    float2* aOo = aEo + ASUB;
    // b sub-arrays alias x region (safe: block barrier between x reads and
    // b writes): fam f at (float2*)sm + f*4*BSUB: bEe,bOe,bEo,bOo

    const int b   = blockIdx.y;
    const int n0  = blockIdx.x * N3;
    const int tid = threadIdx.x;

    float wl[KS], wh[KS];
    #pragma unroll
    for (int k = 0; k < KS; ++k) wl[k] = __ldg(&kern[k]);
    #pragma unroll
    for (int k = 0; k < KS; ++k) wh[k] = (k & 1) ? -wl[KS-1-k] : wl[KS-1-k];
    u64 wp[KS];                                 // (wl,wh) lanes for level 1
    #pragma unroll
    for (int k = 0; k < KS; ++k) wp[k] = pack2(wl[k], wh[k]);

    // ---- Stage x, parity-split; streaming LDG.128 (read-once data) ----
    {
        const int jbase = 8 * n0 - 28;
        const float* xb = x + (size_t)b * T;
        #pragma unroll
        for (int it = 0; it < 4; ++it) {
            const int i4 = it * THREADS + tid;
            float4 v = __ldcs((const float4*)(xb + ((jbase + 4 * i4) & MSK)));
            *(float2*)(xE + 2 * i4) = make_float2(v.x, v.z);
            *(float2*)(xO + 2 * i4) = make_float2(v.y, v.w);
        }
        if (tid < 16) {                        // tail: i4 = 1024..1039
            const int i4 = 1024 + tid;
            float4 v = __ldcs((const float4*)(xb + ((jbase + 4 * i4) & MSK)));
            *(float2*)(xE + 2 * i4) = make_float2(v.x, v.z);
            *(float2*)(xO + 2 * i4) = make_float2(v.y, v.w);
        }
    }
    __syncthreads();

    // ================= Level 1 (f32x2, lanes = (lo,hi)) =================
    {
        float* o1 = out + (size_t)b * (2 * 32768) + 4 * n0;
        if (tid < 6) {                         // halo chunks {0,1,2,515,516,517}
            const int G = (tid < 3) ? tid : 512 + tid;
            float o8[8], e8[8]; u64 acc[4];
            ld8(xO + 4*G, o8);
            ld8(xE + 4*G, e8);
            qmf4f(o8, e8, wp, acc);
            *(u64*)(aEe + G) = acc[0];
            *(u64*)(aOe + G) = acc[1];
            *(u64*)(aEo + G) = acc[2];
            *(u64*)(aOo + G) = acc[3];
        }
        #pragma unroll
        for (int it = 0; it < 2; ++it) {       // owned: G = gp+3, branch-free
            const int gp = it * THREADS + tid;
            const int G  = gp + 3;
            float o8[8], e8[8]; u64 acc[4];
            ld8(xO + 4*G, o8);
            ld8(xE + 4*G, e8);
            qmf4f(o8, e8, wp, acc);
            *(u64*)(aEe + G) = acc[0];
            *(u64*)(aOe + G) = acc[1];
            *(u64*)(aEo + G) = acc[2];
            *(u64*)(aOo + G) = acc[3];
            F2U p0{acc[0]}, p1{acc[1]}, p2{acc[2]}, p3{acc[3]};
            stg4s(o1 + 4*gp,         p0.f.x, p1.f.x, p2.f.x, p3.f.x);
            stg4s(o1 + 32768 + 4*gp, p0.f.y, p1.f.y, p2.f.y, p3.f.y);
        }
    }

    // coefficient pairs for parent-paired levels (built after level 1)
    u64 bl[KS], bh[KS];
    #pragma unroll
    for (int k = 0; k < KS; ++k) { bl[k] = bcast2(wl[k]); bh[k] = bcast2(wh[k]); }

    __syncthreads();

    // ================= Level 2 (f32x2, lanes = (a0,a4)) =================
    {
        float2* f0 = (float2*)sm;              // fam0: bEe,bOe,bEo,bOo
        float2* f1 = f0 + 4 * BSUB;            // fam1
        #pragma unroll
        for (int pass = 0; pass < 2; ++pass) {
            int h; bool owned;
            if (pass == 0) { h = tid + 1; owned = true; }       // h in [1,256]
            else {
                if (tid >= 2) break;
                h = tid ? 257 : 0; owned = false;               // halo
            }
            u64 OE[4], OO[4], EE[4], EO[4];
            ld4p(aOe, 2*h, OE);
            ld4p(aOo, 2*h, OO);
            ld4p(aEe, 2*h, EE);
            ld4p(aEo, 2*h, EO);
            u64 O[8] = {OE[0],OO[0],OE[1],OO[1],OE[2],OO[2],OE[3],OO[3]};
            u64 E[8] = {EE[0],EO[0],EE[1],EO[1],EE[2],EO[2],EE[3],EO[3]};
            u64 aL[4], aH[4];
            qmf4p(O, E, bl, bh, aL, aH);
            *(u64*)(f0 + 0*BSUB + h) = aL[0];
            *(u64*)(f0 + 1*BSUB + h) = aL[1];
            *(u64*)(f0 + 2*BSUB + h) = aL[2];
            *(u64*)(f0 + 3*BSUB + h) = aL[3];
            *(u64*)(f1 + 0*BSUB + h) = aH[0];
            *(u64*)(f1 + 1*BSUB + h) = aH[1];
            *(u64*)(f1 + 2*BSUB + h) = aH[2];
            *(u64*)(f1 + 3*BSUB + h) = aH[3];
            if (owned) {
                // b0->pos0 (L.x), b2->pos1 (H.x), b6->pos2 (H.y), b4->pos3 (L.y)
                float* o2 = out + OUT2_BASE + (size_t)b * (4*16384) + 2*n0 + 4*tid;
                F2U l0{aL[0]}, l1{aL[1]}, l2{aL[2]}, l3{aL[3]};
                F2U h0{aH[0]}, h1{aH[1]}, h2{aH[2]}, h3{aH[3]};
                stg4s(o2 + 0*16384, l0.f.x, l1.f.x, l2.f.x, l3.f.x);
                stg4s(o2 + 1*16384, h0.f.x, h1.f.x, h2.f.x, h3.f.x);
                stg4s(o2 + 2*16384, h0.f.y, h1.f.y, h2.f.y, h3.f.y);
                stg4s(o2 + 3*16384, l0.f.y, l1.f.y, l2.f.y, l3.f.y);
            }
        }
    }
    __syncthreads();

    // ================= Level 3 (f32x2) =================
    // fam0 (b0,b4): cL=(c0,c4)->pos(0,7), cH=(c1,c5)->pos(1,6)
    // fam1 (b2,b6): cL=(c2,c6)->pos(3,4), cH=(c3,c7)->pos(2,5)
    {
        const int fam = tid >> 7;              // warp-uniform
        const int q   = tid & 127;
        const float2* fb = (float2*)sm + (size_t)fam * (4 * BSUB);
        u64 OE[4], OO[4], EE[4], EO[4];
        ld4p(fb + 1*BSUB, 2*q, OE);            // bOe
        ld4p(fb + 3*BSUB, 2*q, OO);            // bOo
        ld4p(fb + 0*BSUB, 2*q, EE);            // bEe
        ld4p(fb + 2*BSUB, 2*q, EO);            // bEo
        u64 O[8] = {OE[0],OO[0],OE[1],OO[1],OE[2],OO[2],OE[3],OO[3]};
        u64 E[8] = {EE[0],EO[0],EE[1],EO[1],EE[2],EO[2],EE[3],EO[3]};
        u64 cL[4], cH[4];
        qmf4p(O, E, bl, bh, cL, cH);
        float* o3 = out + OUT3_BASE + (size_t)b * (8 * 8192) + n0 + 4 * q;
        const int posLx = fam ? 3 : 0, posLy = fam ? 4 : 7;
        const int posHx = fam ? 2 : 1, posHy = fam ? 5 : 6;
        F2U l0{cL[0]}, l1{cL[1]}, l2{cL[2]}, l3{cL[3]};
        F2U h0{cH[0]}, h1{cH[1]}, h2{cH[2]}, h3{cH[3]};
        stg4s(o3 + posLx * 8192, l0.f.x, l1.f.x, l2.f.x, l3.f.x);
        stg4s(o3 + posLy * 8192, l0.f.y, l1.f.y, l2.f.y, l3.f.y);
        stg4s(o3 + posHx * 8192, h0.f.x, h1.f.x, h2.f.x, h3.f.x);
        stg4s(o3 + posHy * 8192, h0.f.y, h1.f.y, h2.f.y, h3.f.y);
    }
}

extern "C" void kernel_launch(void* const* d_in, const int* in_sizes, int n_in,
                              void* d_out, int out_size)
{
    const float* x    = (const float*)d_in[0];
    const float* kern = (const float*)d_in[1];
    float* out        = (float*)d_out;

    cudaFuncSetAttribute(mwpt_kernel,
                         cudaFuncAttributeMaxDynamicSharedMemorySize,
                         SMEM_BYTES);

    dim3 grid(8192 / N3, 128);   // 16 x 128 = 2048 blocks
    mwpt_kernel<<<grid, THREADS, SMEM_BYTES>>>(x, kern, out);
}

// round 17
// speedup vs baseline: 1.1889x; 1.1889x over previous
#include <cuda_runtime.h>

// MWPT: 3-level wavelet packet transform, fused, polyphase smem layout.
// CHAMPION (R15 verbatim; R16's __ldcs reverted -- regressed wall time).
// ALL levels fma.rn.f32x2:
//   level 1: lanes = (lo,hi) filters; accumulator pair IS the stored (a0,a4).
//   levels 2-3: lanes = parent pairs over sub-parity-split arrays
//            (16B-stride LDS, conflict-free), coefficients broadcast.
// __stcs streaming output stores (validated R15: cut L2 dirty-drain tail,
// wall 26.9 -> 23.2us).
//
// conv: out[n] = sum_k in[(2n + k - 3) mod L] * w[k]  (circular, stride 2)
// hi-pass QMF: wh[k] = (-1)^k * wl[7-k]
// out = concat(level1 [128,2,32768], level2 [128,4,16384], level3 [128,8,8192])
// level2 node order [b0,b2,b6,b4]; level3 [c0,c1,c3,c2,c6,c7,c5,c4].
//
// Index algebra (validated R3-R16):
//  x staged from jbase=8n0-28: xE[i]=x[jbase+2i], xO[i]=x[jbase+2i+1]
//  a_alpha (alpha=m-4n0+12) = sum_j xO[alpha+j]wl[2j] + xE[alpha+j+1]wl[2j+1]
//    chunk G: alpha=4G+p; owned G in [3,515); halo {0,1,2,515,516,517}
//    pairs P[alpha]=(a0,a4): aEe[G]=P[4G], aOe[G]=P[4G+1], aEo[G]=P[4G+2], aOo[G]=P[4G+3]
//  b_beta (beta=l-2n0+4): lanes (a0,a4) -> fam0=(b0,b4), fam1=(b2,b6)
//    chunk h: beta=4h+p -> bEe[h],bOe[h],bEo[h],bOo[h]; owned h in [1,257)
//  c_r (r=i-n0) in [0,512): from fam arrays, chunk q: r=4q+p

namespace {
constexpr int T   = 65536, MSK = T - 1, KS = 8;
constexpr int N3  = 512;
constexpr int THREADS = 256;
constexpr int XSZ  = 2080;              // floats per x parity
constexpr int XREG = 2 * XSZ;           // 4160 floats; aliased by b sub-arrays
constexpr int ASUB = 520;               // float2 per a sub-array (518 used), x4
constexpr int BSUB = 260;               // float2 per b sub-array (258 used), x8
constexpr int SMEM_FLOATS = XREG + 4 * ASUB * 2;   // 8320
constexpr int SMEM_BYTES  = SMEM_FLOATS * 4;       // 33280
constexpr long OUT2_BASE = 128L * 2 * 32768;
constexpr long OUT3_BASE = OUT2_BASE + 128L * 4 * 16384;
}

using u64 = unsigned long long;
union F2U { u64 u; float2 f; };

__device__ __forceinline__ u64 bcast2(float a) {
    u64 r; asm("mov.b64 %0, {%1, %1};" : "=l"(r) : "f"(a)); return r;
}
__device__ __forceinline__ u64 pack2(float a, float b) {
    u64 r; asm("mov.b64 %0, {%1, %2};" : "=l"(r) : "f"(a), "f"(b)); return r;
}
__device__ __forceinline__ u64 mul2(u64 a, u64 b) {
    u64 d; asm("mul.rn.f32x2 %0, %1, %2;" : "=l"(d) : "l"(a), "l"(b)); return d;
}
__device__ __forceinline__ void fma2(u64& d, u64 a, u64 b) {
    asm("fma.rn.f32x2 %0, %1, %2, %0;" : "+l"(d) : "l"(a), "l"(b));
}

__device__ __forceinline__ void ld8(const float* s, float v[8]) {
    float4 a = *(const float4*)s;
    float4 b = *(const float4*)(s + 4);
    v[0]=a.x; v[1]=a.y; v[2]=a.z; v[3]=a.w;
    v[4]=b.x; v[5]=b.y; v[6]=b.z; v[7]=b.w;
}
// 4 consecutive float2: 2x LDS.128 at 16B/thread stride (conflict-free).
__device__ __forceinline__ void ld4p(const float2* s, int i, u64 v[4]) {
    const ulonglong2* p = (const ulonglong2*)(s + i);
    ulonglong2 q0 = p[0], q1 = p[1];
    v[0]=q0.x; v[1]=q0.y; v[2]=q1.x; v[3]=q1.y;
}
// streaming 128-bit store (evict-first; output is write-once)
__device__ __forceinline__ void stg4s(float* p, float a, float b, float c, float d) {
    __stcs((float4*)p, make_float4(a, b, c, d));
}

// Level-1 packed chunk: acc[p] = (lo,hi) pair for alpha = 4G+p.
__device__ __forceinline__ void qmf4f(const float o8[8], const float e8[8],
                                      const u64 wp[KS], u64 acc[4]) {
    #pragma unroll
    for (int p = 0; p < 4; ++p) {
        u64 a = mul2(bcast2(o8[p]), wp[0]);     // bcasts CSE across p
        fma2(a, bcast2(e8[p+1]), wp[1]);
        #pragma unroll
        for (int j = 1; j < 4; ++j) {
            fma2(a, bcast2(o8[p+j]),   wp[2*j]);
            fma2(a, bcast2(e8[p+j+1]), wp[2*j+1]);
        }
        acc[p] = a;
    }
}

// packed 2-lane QMF (lanes = two parent nodes, coefficients broadcast)
__device__ __forceinline__ void qmf4p(const u64 O[8], const u64 E[8],
                                      const u64 bl[KS], const u64 bh[KS],
                                      u64 aL[4], u64 aH[4]) {
    #pragma unroll
    for (int p = 0; p < 4; ++p) {
        u64 l = mul2(O[p], bl[0]);
        u64 h = mul2(O[p], bh[0]);
        fma2(l, E[p+1], bl[1]);
        fma2(h, E[p+1], bh[1]);
        #pragma unroll
        for (int j = 1; j < 4; ++j) {
            fma2(l, O[p+j],   bl[2*j]);   fma2(l, E[p+j+1], bl[2*j+1]);
            fma2(h, O[p+j],   bh[2*j]);   fma2(h, E[p+j+1], bh[2*j+1]);
        }
        aL[p] = l; aH[p] = h;
    }
}

__global__ __launch_bounds__(THREADS, 4) void mwpt_kernel(
    const float* __restrict__ x,
    const float* __restrict__ kern,
    float* __restrict__ out)
{
    extern __shared__ float sm[];
    float*  xE  = sm;                          // [XSZ]
    float*  xO  = sm + XSZ;                    // [XSZ]
    float2* aEe = (float2*)(sm + XREG);        // [ASUB] each
    float2* aOe = aEe + ASUB;
    float2* aEo = aOe + ASUB;
    float2* aOo = aEo + ASUB;
    // b sub-arrays alias x region (safe: block barrier between x reads and
    // b writes): fam f at (float2*)sm + f*4*BSUB: bEe,bOe,bEo,bOo

    const int b   = blockIdx.y;
    const int n0  = blockIdx.x * N3;
    const int tid = threadIdx.x;

    float wl[KS], wh[KS];
    #pragma unroll
    for (int k = 0; k < KS; ++k) wl[k] = __ldg(&kern[k]);
    #pragma unroll
    for (int k = 0; k < KS; ++k) wh[k] = (k & 1) ? -wl[KS-1-k] : wl[KS-1-k];
    u64 wp[KS];                                 // (wl,wh) lanes for level 1
    #pragma unroll
    for (int k = 0; k < KS; ++k) wp[k] = pack2(wl[k], wh[k]);

    // ---- Stage x, parity-split (aligned LDG.128); 4 full trips + tail ----
    {
        const int jbase = 8 * n0 - 28;
        const float* xb = x + (size_t)b * T;
        #pragma unroll
        for (int it = 0; it < 4; ++it) {
            const int i4 = it * THREADS + tid;
            float4 v = *(const float4*)(xb + ((jbase + 4 * i4) & MSK));
            *(float2*)(xE + 2 * i4) = make_float2(v.x, v.z);
            *(float2*)(xO + 2 * i4) = make_float2(v.y, v.w);
        }
        if (tid < 16) {                        // tail: i4 = 1024..1039
            const int i4 = 1024 + tid;
            float4 v = *(const float4*)(xb + ((jbase + 4 * i4) & MSK));
            *(float2*)(xE + 2 * i4) = make_float2(v.x, v.z);
            *(float2*)(xO + 2 * i4) = make_float2(v.y, v.w);
        }
    }
    __syncthreads();

    // ================= Level 1 (f32x2, lanes = (lo,hi)) =================
    {
        float* o1 = out + (size_t)b * (2 * 32768) + 4 * n0;
        if (tid < 6) {                         // halo chunks {0,1,2,515,516,517}
            const int G = (tid < 3) ? tid : 512 + tid;
            float o8[8], e8[8]; u64 acc[4];
            ld8(xO + 4*G, o8);
            ld8(xE + 4*G, e8);
            qmf4f(o8, e8, wp, acc);
            *(u64*)(aEe + G) = acc[0];
            *(u64*)(aOe + G) = acc[1];
            *(u64*)(aEo + G) = acc[2];
            *(u64*)(aOo + G) = acc[3];
        }
        #pragma unroll
        for (int it = 0; it < 2; ++it) {       // owned: G = gp+3, branch-free
            const int gp = it * THREADS + tid;
            const int G  = gp + 3;
            float o8[8], e8[8]; u64 acc[4];
            ld8(xO + 4*G, o8);
            ld8(xE + 4*G, e8);
            qmf4f(o8, e8, wp, acc);
            *(u64*)(aEe + G) = acc[0];
            *(u64*)(aOe + G) = acc[1];
            *(u64*)(aEo + G) = acc[2];
            *(u64*)(aOo + G) = acc[3];
            F2U p0{acc[0]}, p1{acc[1]}, p2{acc[2]}, p3{acc[3]};
            stg4s(o1 + 4*gp,         p0.f.x, p1.f.x, p2.f.x, p3.f.x);
            stg4s(o1 + 32768 + 4*gp, p0.f.y, p1.f.y, p2.f.y, p3.f.y);
        }
    }

    // coefficient pairs for parent-paired levels (built after level 1)
    u64 bl[KS], bh[KS];
    #pragma unroll
    for (int k = 0; k < KS; ++k) { bl[k] = bcast2(wl[k]); bh[k] = bcast2(wh[k]); }

    __syncthreads();

    // ================= Level 2 (f32x2, lanes = (a0,a4)) =================
    {
        float2* f0 = (float2*)sm;              // fam0: bEe,bOe,bEo,bOo
        float2* f1 = f0 + 4 * BSUB;            // fam1
        #pragma unroll
        for (int pass = 0; pass < 2; ++pass) {
            int h; bool owned;
            if (pass == 0) { h = tid + 1; owned = true; }       // h in [1,256]
            else {
                if (tid >= 2) break;
                h = tid ? 257 : 0; owned = false;               // halo
            }
            u64 OE[4], OO[4], EE[4], EO[4];
            ld4p(aOe, 2*h, OE);
            ld4p(aOo, 2*h, OO);
            ld4p(aEe, 2*h, EE);
            ld4p(aEo, 2*h, EO);
            u64 O[8] = {OE[0],OO[0],OE[1],OO[1],OE[2],OO[2],OE[3],OO[3]};
            u64 E[8] = {EE[0],EO[0],EE[1],EO[1],EE[2],EO[2],EE[3],EO[3]};
            u64 aL[4], aH[4];
            qmf4p(O, E, bl, bh, aL, aH);
            *(u64*)(f0 + 0*BSUB + h) = aL[0];
            *(u64*)(f0 + 1*BSUB + h) = aL[1];
            *(u64*)(f0 + 2*BSUB + h) = aL[2];
            *(u64*)(f0 + 3*BSUB + h) = aL[3];
            *(u64*)(f1 + 0*BSUB + h) = aH[0];
            *(u64*)(f1 + 1*BSUB + h) = aH[1];
            *(u64*)(f1 + 2*BSUB + h) = aH[2];
            *(u64*)(f1 + 3*BSUB + h) = aH[3];
            if (owned) {
                // b0->pos0 (L.x), b2->pos1 (H.x), b6->pos2 (H.y), b4->pos3 (L.y)
                float* o2 = out + OUT2_BASE + (size_t)b * (4*16384) + 2*n0 + 4*tid;
                F2U l0{aL[0]}, l1{aL[1]}, l2{aL[2]}, l3{aL[3]};
                F2U h0{aH[0]}, h1{aH[1]}, h2{aH[2]}, h3{aH[3]};
                stg4s(o2 + 0*16384, l0.f.x, l1.f.x, l2.f.x, l3.f.x);
                stg4s(o2 + 1*16384, h0.f.x, h1.f.x, h2.f.x, h3.f.x);
                stg4s(o2 + 2*16384, h0.f.y, h1.f.y, h2.f.y, h3.f.y);
                stg4s(o2 + 3*16384, l0.f.y, l1.f.y, l2.f.y, l3.f.y);
            }
        }
    }
    __syncthreads();

    // ================= Level 3 (f32x2) =================
    // fam0 (b0,b4): cL=(c0,c4)->pos(0,7), cH=(c1,c5)->pos(1,6)
    // fam1 (b2,b6): cL=(c2,c6)->pos(3,4), cH=(c3,c7)->pos(2,5)
    {
        const int fam = tid >> 7;              // warp-uniform
        const int q   = tid & 127;
        const float2* fb = (float2*)sm + (size_t)fam * (4 * BSUB);
        u64 OE[4], OO[4], EE[4], EO[4];
        ld4p(fb + 1*BSUB, 2*q, OE);            // bOe
        ld4p(fb + 3*BSUB, 2*q, OO);            // bOo
        ld4p(fb + 0*BSUB, 2*q, EE);            // bEe
        ld4p(fb + 2*BSUB, 2*q, EO);            // bEo
        u64 O[8] = {OE[0],OO[0],OE[1],OO[1],OE[2],OO[2],OE[3],OO[3]};
        u64 E[8] = {EE[0],EO[0],EE[1],EO[1],EE[2],EO[2],EE[3],EO[3]};
        u64 cL[4], cH[4];
        qmf4p(O, E, bl, bh, cL, cH);
        float* o3 = out + OUT3_BASE + (size_t)b * (8 * 8192) + n0 + 4 * q;
        const int posLx = fam ? 3 : 0, posLy = fam ? 4 : 7;
        const int posHx = fam ? 2 : 1, posHy = fam ? 5 : 6;
        F2U l0{cL[0]}, l1{cL[1]}, l2{cL[2]}, l3{cL[3]};
        F2U h0{cH[0]}, h1{cH[1]}, h2{cH[2]}, h3{cH[3]};
        stg4s(o3 + posLx * 8192, l0.f.x, l1.f.x, l2.f.x, l3.f.x);
        stg4s(o3 + posLy * 8192, l0.f.y, l1.f.y, l2.f.y, l3.f.y);
        stg4s(o3 + posHx * 8192, h0.f.x, h1.f.x, h2.f.x, h3.f.x);
        stg4s(o3 + posHy * 8192, h0.f.y, h1.f.y, h2.f.y, h3.f.y);
    }
}

extern "C" void kernel_launch(void* const* d_in, const int* in_sizes, int n_in,
                              void* d_out, int out_size)
{
    const float* x    = (const float*)d_in[0];
    const float* kern = (const float*)d_in[1];
    float* out        = (float*)d_out;

    cudaFuncSetAttribute(mwpt_kernel,
                         cudaFuncAttributeMaxDynamicSharedMemorySize,
                         SMEM_BYTES);

    dim3 grid(8192 / N3, 128);   // 16 x 128 = 2048 blocks
    mwpt_kernel<<<grid, THREADS, SMEM_BYTES>>>(x, kern, out);
}